// round 3
// baseline (speedup 1.0000x reference)
#include <cuda_runtime.h>

#define KTAGS 48
#define TLEN 1024
#define STOPID 47
#define NEGV (-10000.0f)

__device__ __forceinline__ unsigned long long pk2(float lo, float hi) {
    unsigned long long r;
    asm("mov.b64 %0, {%1, %2};" : "=l"(r) : "f"(lo), "f"(hi));
    return r;
}
__device__ __forceinline__ void upk2(unsigned long long v, float& lo, float& hi) {
    asm("mov.b64 {%0, %1}, %2;" : "=f"(lo), "=f"(hi) : "l"(v));
}
// d = a*b + d  (packed f32x2 -> SASS FFMA2)
__device__ __forceinline__ void fma2(unsigned long long& d, unsigned long long a, unsigned long long b) {
    asm("fma.rn.f32x2 %0, %1, %2, %0;" : "+l"(d) : "l"(a), "l"(b));
}
__device__ __forceinline__ void add2(unsigned long long& d, unsigned long long a) {
    asm("add.rn.f32x2 %0, %0, %1;" : "+l"(d) : "l"(a));
}

__global__ __launch_bounds__(128, 1)
void CRF_29265907155259_kernel(const float* __restrict__ h_tag,
                               const float* __restrict__ mask,
                               const float* __restrict__ trans,
                               float* __restrict__ out, int B)
{
    __shared__ __align__(16) float vbuf[4][2][KTAGS];
    const int lane = threadIdx.x & 31;
    const int warp = threadIdx.x >> 5;
    const int b = blockIdx.x * 4 + warp;
    if (b >= B) return;

    const bool hasB = (lane < 16);
    const int tagA = lane;
    const int tagB = hasB ? (lane + 32) : 0;

    // ---- precompute E = exp(trans) rows in registers (packed pairs) ----
    unsigned long long EA2[24], EB2[24];
    float rowsumA = 0.f, rowsumB = 0.f;
    #pragma unroll
    for (int k = 0; k < 24; ++k) {
        float a0 = __expf(trans[tagA * KTAGS + 2 * k]);
        float a1 = __expf(trans[tagA * KTAGS + 2 * k + 1]);
        rowsumA += a0 + a1;
        EA2[k] = pk2(a0, a1);
        float b0 = hasB ? __expf(trans[tagB * KTAGS + 2 * k])     : 0.f;
        float b1 = hasB ? __expf(trans[tagB * KTAGS + 2 * k + 1]) : 0.f;
        rowsumB += b0 + b1;
        EB2[k] = pk2(b0, b1);
    }
    const float EfinA = __expf(trans[STOPID * KTAGS + tagA]);
    const float EfinB = hasB ? __expf(trans[STOPID * KTAGS + tagB]) : 0.f;

    const float* eb = h_tag + (size_t)b * TLEN * KTAGS;
    const float* mb = mask + (size_t)b * TLEN;

    // ---- special step t = 0 (log domain, exact; exp-domain would underflow) ----
    // s1_i = NEG + log(1 + sum_j E_ij) + emit_0i   (score0: 0 at STOP, NEG else)
    float e0A = eb[lane];
    float e0B = hasB ? eb[32 + lane] : 0.f;
    float m0 = mb[0];
    float sA = NEGV + __logf(1.0f + rowsumA) + e0A;
    float sB = NEGV + __logf(1.0f + rowsumB) + e0B;
    sA = (m0 != 0.f) ? sA : NEGV;                       // tagA in [0,32): never STOP
    sB = (m0 != 0.f) ? sB : ((tagB == STOPID) ? 0.f : NEGV);
    float loc = fmaxf(sA, hasB ? sB : -3.0e38f);
    #pragma unroll
    for (int o = 16; o; o >>= 1)
        loc = fmaxf(loc, __shfl_xor_sync(0xffffffffu, loc, o));
    double M = (double)loc;
    float vA = __expf(sA - loc);
    float vB = hasB ? __expf(sB - loc) : 0.f;

    float* vcur = &vbuf[warp][0][0];
    float* vnxt = &vbuf[warp][1][0];
    vcur[lane] = vA;
    if (hasB) vcur[32 + lane] = vB;

    // ---- emit/mask prefetch, one 4-step group ahead ----
    float nA[4], nB[4], nM[4];
    #pragma unroll
    for (int u = 0; u < 4; ++u) {
        int t = 1 + u;
        nA[u] = eb[t * KTAGS + lane];
        nB[u] = hasB ? eb[t * KTAGS + 32 + lane] : 0.f;
        nM[u] = mb[t];
    }

    for (int base = 1; base < TLEN; base += 4) {
        float cA[4], cB[4], cM[4];
        #pragma unroll
        for (int u = 0; u < 4; ++u) { cA[u] = nA[u]; cB[u] = nB[u]; cM[u] = nM[u]; }
        #pragma unroll
        for (int u = 0; u < 4; ++u) {
            int t = base + 4 + u;
            int tc = (t < TLEN) ? t : (TLEN - 1);
            nA[u] = eb[tc * KTAGS + lane];
            nB[u] = hasB ? eb[tc * KTAGS + 32 + lane] : 0.f;
            nM[u] = mb[tc];
        }
        #pragma unroll
        for (int u = 0; u < 4; ++u) {
            int t = base + u;
            if (t >= TLEN) break;
            float eEA = __expf(cA[u]);
            float eEB = hasB ? __expf(cB[u]) : 0.f;

            __syncwarp();
            const ulonglong2* vp = (const ulonglong2*)vcur;
            unsigned long long aA[6] = {0, 0, 0, 0, 0, 0};
            unsigned long long aB[6] = {0, 0, 0, 0, 0, 0};
            #pragma unroll
            for (int k = 0; k < 12; ++k) {
                ulonglong2 w = vp[k];
                fma2(aA[(2 * k) % 6],     EA2[2 * k],     w.x);
                fma2(aA[(2 * k + 1) % 6], EA2[2 * k + 1], w.y);
                fma2(aB[(2 * k) % 6],     EB2[2 * k],     w.x);
                fma2(aB[(2 * k + 1) % 6], EB2[2 * k + 1], w.y);
            }
            add2(aA[0], aA[3]); add2(aA[1], aA[4]); add2(aA[2], aA[5]);
            add2(aA[0], aA[1]); add2(aA[0], aA[2]);
            add2(aB[0], aB[3]); add2(aB[1], aB[4]); add2(aB[2], aB[5]);
            add2(aB[0], aB[1]); add2(aB[0], aB[2]);
            float xl, xh, yl, yh;
            upk2(aA[0], xl, xh);
            upk2(aB[0], yl, yh);
            float dotA = xl + xh;
            float dotB = yl + yh;

            float rawA = dotA * eEA;
            float rawB = dotB * eEB;
            bool live = (cM[u] != 0.f);
            vA = live ? rawA : vA;
            vB = live ? rawB : vB;

            if ((u == 3) || (t == TLEN - 1)) {
                // all v >= 0 -> float max == uint max
                float lmax = fmaxf(vA, vB);
                float mx = __uint_as_float(__reduce_max_sync(0xffffffffu, __float_as_uint(lmax)));
                float r = __fdividef(1.0f, mx);
                vA *= r;
                vB *= r;
                M += (double)__logf(mx);
            }
            vnxt[lane] = vA;
            if (hasB) vnxt[32 + lane] = vB;
            float* tp = vcur; vcur = vnxt; vnxt = tp;
        }
    }

    // ---- finalize: out = M + log(sum_i v_i * exp(trans[STOP, i])) ----
    float fin = vA * EfinA + vB * EfinB;
    #pragma unroll
    for (int o = 16; o; o >>= 1)
        fin += __shfl_xor_sync(0xffffffffu, fin, o);
    if (lane == 0) out[b] = (float)(M + (double)__logf(fin));
}

extern "C" void kernel_launch(void* const* d_in, const int* in_sizes, int n_in,
                              void* d_out, int out_size) {
    const float* h_tag = (const float*)d_in[0];
    const float* msk   = (const float*)d_in[1];
    const float* trans = (const float*)d_in[2];
    float* out = (float*)d_out;
    int B = in_sizes[0] / (TLEN * KTAGS);
    int blocks = (B + 3) / 4;
    CRF_29265907155259_kernel<<<blocks, 128>>>(h_tag, msk, trans, out, B);
}